// round 11
// baseline (speedup 1.0000x reference)
#include <cuda_runtime.h>
#include <cstdint>

#define S_LEN 16384
#define D_DIM 256
#define V_DIM 8
#define K_HEADS 24
#define NBUCKET 1024            // 131072 rows / 1024 = 128 rows (128KB) per bucket

// Scratch (static __device__ allocations are allowed)
__device__ unsigned int g_sorted[K_HEADS * S_LEN];
__device__ int g_base[K_HEADS][NBUCKET];
__device__ int g_cursor[K_HEADS][NBUCKET];

// ---- Pass 1: per-head histogram over 1024 index buckets.
__global__ void hist_kernel(const int* __restrict__ mask_idx) {
    __shared__ int h[NBUCKET];
    const int k = blockIdx.x;
    for (int b = threadIdx.x; b < NBUCKET; b += blockDim.x) h[b] = 0;
    __syncthreads();
    for (int s = threadIdx.x; s < S_LEN; s += blockDim.x) {
        int idx = mask_idx[k * S_LEN + s];
        atomicAdd(&h[idx >> 7], 1);
    }
    __syncthreads();
    for (int b = threadIdx.x; b < NBUCKET; b += blockDim.x)
        g_base[k][b] = h[b];
}

// ---- Pass 2: exclusive scan per head (1024 threads, Hillis-Steele).
__global__ void scan_kernel() {
    __shared__ int sh[NBUCKET];
    const int k = blockIdx.x, t = threadIdx.x;
    const int v = g_base[k][t];
    sh[t] = v;
    __syncthreads();
    #pragma unroll
    for (int off = 1; off < NBUCKET; off <<= 1) {
        int add = (t >= off) ? sh[t - off] : 0;
        __syncthreads();
        sh[t] += add;
        __syncthreads();
    }
    const int excl = sh[t] - v;
    g_base[k][t] = excl;
    g_cursor[k][t] = excl;
}

// ---- Pass 3: scatter records (s:14b << 17 | idx:17b) into bucket order.
__global__ void scatter_kernel(const int* __restrict__ mask_idx) {
    const int k = blockIdx.x;
    for (int s = threadIdx.x; s < S_LEN; s += blockDim.x) {
        int idx = mask_idx[k * S_LEN + s];
        int pos = atomicAdd(&g_cursor[k][idx >> 7], 1);
        g_sorted[k * S_LEN + pos] = ((unsigned)s << 17) | (unsigned)idx;
    }
}

__device__ __forceinline__ unsigned long long packf2(float lo, float hi) {
    unsigned long long r;
    asm("mov.b64 %0, {%1, %2};" : "=l"(r) : "f"(lo), "f"(hi));
    return r;
}
__device__ __forceinline__ void unpackf2(unsigned long long p, float& lo, float& hi) {
    asm("mov.b64 {%0, %1}, %2;" : "=f"(lo), "=f"(hi) : "l"(p));
}
__device__ __forceinline__ void fmaf2(unsigned long long& d, unsigned long long a,
                                      unsigned long long b) {
    asm("fma.rn.f32x2 %0, %1, %2, %0;" : "+l"(d) : "l"(a), "l"(b));
}

// ---- Main: R6 engine, consuming the locality-sorted stream.
__global__ __launch_bounds__(256, 2)
void attr_decoder_kernel(const float* __restrict__ feats,      // [N, 256]
                         const float* __restrict__ Wh,         // [24, 256, 8]
                         const float* __restrict__ bias,       // [24, 8]
                         float*       __restrict__ out)        // [24, 16384, 8]
{
    const int k    = blockIdx.x;                      // head (fast grid dim ->
    const int lane = threadIdx.x & 31;                //  all heads run the same
    const int warp = threadIdx.x >> 5;                //  table window at once)
    const int s0   = blockIdx.y * 256 + warp * 32;

    // Weights: coalesced lane->d map {4*lane+j} U {128+4*lane+j}, f32x2 by v-pair.
    unsigned long long wp[8][4];
    const float4* wk = (const float4*)(Wh + (size_t)k * (D_DIM * V_DIM));
    #pragma unroll
    for (int i = 0; i < 8; ++i) {
        int d = (i < 4) ? (4 * lane + i) : (128 + 4 * lane + (i - 4));
        float4 A = wk[d * 2 + 0];
        float4 B = wk[d * 2 + 1];
        wp[i][0] = packf2(A.x, A.y);
        wp[i][1] = packf2(A.z, A.w);
        wp[i][2] = packf2(B.x, B.y);
        wp[i][3] = packf2(B.z, B.w);
    }
    const int  vown   = (lane >> 2) & 7;
    const float bias_v = bias[k * V_DIM + vown];

    // One sorted record per lane covers the warp's 32 work items.
    const unsigned recv = g_sorted[(size_t)k * S_LEN + s0 + lane];

    // Row 0: broadcast record, split idx / original s.
    unsigned rec0 = __shfl_sync(0xffffffffu, recv, 0);
    int sout_cur = rec0 >> 17;
    const float4* fr0 = (const float4*)(feats + (size_t)(rec0 & 0x1FFFF) * D_DIM);
    float4 fa = fr0[lane];
    float4 fb = fr0[32 + lane];

    const bool b4 = (lane & 16) != 0;
    const bool b3 = (lane & 8)  != 0;
    const bool b2 = (lane & 4)  != 0;

    #pragma unroll 4
    for (int r = 0; r < 32; ++r) {
        const float4 ca = fa, cb = fb;
        int sout_nxt = 0;
        if (r + 1 < 32) {   // depth-1 prefetch (sorted -> mostly L2/L1 hits now)
            unsigned rn = __shfl_sync(0xffffffffu, recv, r + 1);
            sout_nxt = rn >> 17;
            const float4* nf = (const float4*)(feats + (size_t)(rn & 0x1FFFF) * D_DIM);
            fa = nf[lane];
            fb = nf[32 + lane];
        }

        // Packed FMA: acc[p] = partial (v=2p, v=2p+1) over this lane's 8 d's.
        const float f[8] = {ca.x, ca.y, ca.z, ca.w, cb.x, cb.y, cb.z, cb.w};
        unsigned long long acc[4] = {0ull, 0ull, 0ull, 0ull};
        #pragma unroll
        for (int i = 0; i < 8; ++i) {
            unsigned long long fd = packf2(f[i], f[i]);
            #pragma unroll
            for (int p = 0; p < 4; ++p) fmaf2(acc[p], fd, wp[i][p]);
        }
        float a[8];
        #pragma unroll
        for (int p = 0; p < 4; ++p) unpackf2(acc[p], a[2 * p], a[2 * p + 1]);

        // Fold-first reduce-scatter (R2/R6 schedule, 9 shfl).
        float t[4];
        #pragma unroll
        for (int j = 0; j < 4; ++j) {
            float keep = b4 ? a[4 + j] : a[j];
            float send = b4 ? a[j]     : a[4 + j];
            t[j] = keep + __shfl_xor_sync(0xffffffffu, send, 16);
        }
        float u[2];
        #pragma unroll
        for (int j = 0; j < 2; ++j) {
            float keep = b3 ? t[2 + j] : t[j];
            float send = b3 ? t[j]     : t[2 + j];
            u[j] = keep + __shfl_xor_sync(0xffffffffu, send, 8);
        }
        float keep = b2 ? u[1] : u[0];
        float send = b2 ? u[0] : u[1];
        float w = keep + __shfl_xor_sync(0xffffffffu, send, 4);
        w += __shfl_xor_sync(0xffffffffu, w, 2);
        w += __shfl_xor_sync(0xffffffffu, w, 1);
        const float res = w + bias_v;   // lane l holds v=(l>>2)&7, replica over l&3

        // Scattered per-row store: replica group 0 (lanes 4v) writes one
        // contiguous 32B sector at out[k, s_orig, :].
        if ((lane & 3) == 0) {
            out[((size_t)k * S_LEN + sout_cur) * V_DIM + vown] = res;
        }
        sout_cur = sout_nxt;
    }
}

extern "C" void kernel_launch(void* const* d_in, const int* in_sizes, int n_in,
                              void* d_out, int out_size) {
    // metadata order: block_type_grid (unused), features, mask_idx, head_weights, head_bias
    const float* feats    = (const float*)d_in[1];
    const int*   mask_idx = (const int*)  d_in[2];
    const float* Wh       = (const float*)d_in[3];
    const float* bias     = (const float*)d_in[4];
    float*       out      = (float*)d_out;

    hist_kernel<<<K_HEADS, 256>>>(mask_idx);
    scan_kernel<<<K_HEADS, NBUCKET>>>();
    scatter_kernel<<<K_HEADS, 256>>>(mask_idx);
    attr_decoder_kernel<<<dim3(K_HEADS, S_LEN / 256), 256>>>(feats, Wh, bias, out);
}

// round 13
// speedup vs baseline: 2.1887x; 2.1887x over previous
#include <cuda_runtime.h>
#include <cstdint>

#define S_LEN 16384
#define D_DIM 256
#define V_DIM 8
#define K_HEADS 24
#define ROW_F 260                            // padded smem row stride (floats)
#define ROWS_PER_WARP 16
#define WARPS_CTA 4
#define ROWS_CTA (ROWS_PER_WARP * WARPS_CTA) // 64
#define SMEM_BYTES (ROWS_CTA * ROW_F * 4)    // 66560 B

__device__ __forceinline__ uint32_t f2tf32(float f) {
    uint32_t u;
    asm("cvt.rna.tf32.f32 %0, %1;" : "=r"(u) : "f"(f));
    return u;
}

__global__ __launch_bounds__(128, 3)
void attr_decoder_hmma(const float* __restrict__ feats,      // [N, 256]
                       const int*   __restrict__ mask_idx,   // [24, 16384]
                       const float* __restrict__ Wh,         // [24, 256, 8]
                       const float* __restrict__ bias,       // [24, 8]
                       float*       __restrict__ out)        // [24, 16384, 8]
{
    extern __shared__ __align__(16) float smem[];
    const int k    = blockIdx.y;
    const int lane = threadIdx.x & 31;
    const int warp = threadIdx.x >> 5;
    const int s0w  = blockIdx.x * ROWS_CTA + warp * ROWS_PER_WARP;

    const int tg  = lane & 3;    // threadID_in_group (k-col / out-col pair)
    const int gid = lane >> 2;   // groupID (row within half-tile / v for B)

    // Index for this warp's 16 rows (lane&15 keeps reads in-bounds everywhere).
    const int idxv = mask_idx[(size_t)k * S_LEN + s0w + (lane & 15)];

    // ---- 1. Warp-autonomous gather: 16 rows x 1KB via cp.async.
    // Each j copies one contiguous 512B run of one row (32 lanes x 16B).
    float* wbase = smem + warp * ROWS_PER_WARP * ROW_F;
    #pragma unroll
    for (int j = 0; j < 32; ++j) {
        const int r = j >> 1;
        const int i = __shfl_sync(0xffffffffu, idxv, r);
        const int chunk = (j & 1) * 32 + lane;               // 16B chunk in row
        const float* src = feats + (size_t)i * D_DIM + chunk * 4;
        uint32_t dst = (uint32_t)__cvta_generic_to_shared(
            wbase + r * ROW_F + chunk * 4);
        asm volatile("cp.async.cg.shared.global [%0], [%1], 16;"
                     :: "r"(dst), "l"(src));
    }
    asm volatile("cp.async.commit_group;" ::: "memory");

    // ---- 2. B fragments (weights) for all 32 K-steps, loaded DURING the
    // gather flight. b0: (k=tg, n=gid); b1: (k=tg+4, n=gid). 64 regs.
    const float* wb = Wh + (size_t)k * (D_DIM * V_DIM);
    uint32_t b0[32], b1[32];
    #pragma unroll
    for (int kk = 0; kk < 32; ++kk) {
        b0[kk] = f2tf32(wb[(kk * 8 + tg    ) * V_DIM + gid]);
        b1[kk] = f2tf32(wb[(kk * 8 + tg + 4) * V_DIM + gid]);
    }
    const float bv0 = bias[k * V_DIM + 2 * tg];
    const float bv1 = bias[k * V_DIM + 2 * tg + 1];

    // ---- 3. Complete gather; make all lanes' copies visible.
    asm volatile("cp.async.wait_group 0;" ::: "memory");
    __syncwarp();

    // ---- 4. 32 x mma.sync m16n8k8 tf32, two alternating accumulators.
    // A-frag LDS: base (row gid, col tg); stride-260 padding makes the
    // 32-lane access pattern hit bank == lane (conflict-free).
    const float* arow = wbase + gid * ROW_F + tg;
    float e0 = 0.f, e1 = 0.f, e2 = 0.f, e3 = 0.f;
    float q0 = 0.f, q1 = 0.f, q2 = 0.f, q3 = 0.f;
    #pragma unroll
    for (int kk = 0; kk < 32; ++kk) {
        const float* p = arow + kk * 8;
        uint32_t a0 = f2tf32(p[0]);
        uint32_t a2 = f2tf32(p[4]);
        uint32_t a1 = f2tf32(p[8 * ROW_F]);
        uint32_t a3 = f2tf32(p[8 * ROW_F + 4]);
        if (kk & 1) {
            asm("mma.sync.aligned.m16n8k8.row.col.f32.tf32.tf32.f32 "
                "{%0,%1,%2,%3}, {%4,%5,%6,%7}, {%8,%9}, {%0,%1,%2,%3};"
                : "+f"(q0), "+f"(q1), "+f"(q2), "+f"(q3)
                : "r"(a0), "r"(a1), "r"(a2), "r"(a3), "r"(b0[kk]), "r"(b1[kk]));
        } else {
            asm("mma.sync.aligned.m16n8k8.row.col.f32.tf32.tf32.f32 "
                "{%0,%1,%2,%3}, {%4,%5,%6,%7}, {%8,%9}, {%0,%1,%2,%3};"
                : "+f"(e0), "+f"(e1), "+f"(e2), "+f"(e3)
                : "r"(a0), "r"(a1), "r"(a2), "r"(a3), "r"(b0[kk]), "r"(b1[kk]));
        }
    }

    // ---- 5. Epilogue: combine accumulators + bias; float2 stores.
    // D layout: (row gid, cols 2tg,2tg+1) and (row gid+8, same cols).
    const float d0 = e0 + q0 + bv0;
    const float d1 = e1 + q1 + bv1;
    const float d2 = e2 + q2 + bv0;
    const float d3 = e3 + q3 + bv1;
    float2* o_lo = (float2*)(out + ((size_t)k * S_LEN + s0w + gid) * V_DIM + 2 * tg);
    float2* o_hi = (float2*)(out + ((size_t)k * S_LEN + s0w + gid + 8) * V_DIM + 2 * tg);
    *o_lo = make_float2(d0, d1);
    *o_hi = make_float2(d2, d3);
}

extern "C" void kernel_launch(void* const* d_in, const int* in_sizes, int n_in,
                              void* d_out, int out_size) {
    // metadata order: block_type_grid (unused), features, mask_idx, head_weights, head_bias
    const float* feats    = (const float*)d_in[1];
    const int*   mask_idx = (const int*)  d_in[2];
    const float* Wh       = (const float*)d_in[3];
    const float* bias     = (const float*)d_in[4];
    float*       out      = (float*)d_out;

    cudaFuncSetAttribute(attr_decoder_hmma,
                         cudaFuncAttributeMaxDynamicSharedMemorySize, SMEM_BYTES);
    dim3 grid(S_LEN / ROWS_CTA, K_HEADS);   // 256 x 24 CTAs, 64 rows each
    attr_decoder_hmma<<<grid, 128, SMEM_BYTES>>>(feats, mask_idx, Wh, bias, out);
}

// round 14
// speedup vs baseline: 2.4153x; 1.1035x over previous
#include <cuda_runtime.h>
#include <cstdint>

#define S_LEN 16384
#define D_DIM 256
#define V_DIM 8
#define K_HEADS 24
#define ROW_F 260                            // padded smem row stride (floats, 1040B)
#define ROWS_PER_WARP 16
#define WARPS_CTA 4
#define ROWS_CTA (ROWS_PER_WARP * WARPS_CTA) // 64
#define MBAR_BYTES 128                       // 4 warp mbarriers (8B each, padded)
#define TILE_BYTES (ROWS_PER_WARP * ROW_F * 4)
#define SMEM_BYTES (MBAR_BYTES + WARPS_CTA * TILE_BYTES)   // 128 + 66560

__device__ __forceinline__ uint32_t f2tf32(float f) {
    uint32_t u;
    asm("cvt.rna.tf32.f32 %0, %1;" : "=r"(u) : "f"(f));
    return u;
}

__global__ __launch_bounds__(128, 3)
void attr_decoder_hmma(const float* __restrict__ feats,      // [N, 256]
                       const int*   __restrict__ mask_idx,   // [24, 16384]
                       const float* __restrict__ Wh,         // [24, 256, 8]
                       const float* __restrict__ bias,       // [24, 8]
                       float*       __restrict__ out)        // [24, 16384, 8]
{
    extern __shared__ __align__(16) char smem[];
    const int k    = blockIdx.y;
    const int lane = threadIdx.x & 31;
    const int warp = threadIdx.x >> 5;
    const int s0w  = blockIdx.x * ROWS_CTA + warp * ROWS_PER_WARP;

    const int tg  = lane & 3;    // threadID_in_group (k-col / out-col pair)
    const int gid = lane >> 2;   // groupID (row within half-tile / v for B)

    const uint32_t mbar = (uint32_t)__cvta_generic_to_shared(smem) + warp * 32;
    float* wbase = (float*)(smem + MBAR_BYTES + warp * TILE_BYTES);

    // ---- 1. Per-warp mbarrier init (warp-private -> __syncwarp suffices).
    if (lane == 0) {
        asm volatile("mbarrier.init.shared.b64 [%0], 1;" :: "r"(mbar) : "memory");
        asm volatile("mbarrier.arrive.expect_tx.shared.b64 _, [%0], %1;"
                     :: "r"(mbar), "r"(ROWS_PER_WARP * 1024u) : "memory");
    }
    __syncwarp();

    // ---- 2. Bulk gather: ONE cp.async.bulk per 1KB row (16 total, lanes 0-15).
    // Replaces 1024 per-lane cp.async ops -> LSU cost/tile collapses.
    if (lane < ROWS_PER_WARP) {
        const int idx = mask_idx[(size_t)k * S_LEN + s0w + lane];
        const float* src = feats + (size_t)idx * D_DIM;
        uint32_t dst = (uint32_t)__cvta_generic_to_shared(wbase + lane * ROW_F);
        asm volatile(
            "cp.async.bulk.shared::cta.global.mbarrier::complete_tx::bytes "
            "[%0], [%1], %2, [%3];"
            :: "r"(dst), "l"(src), "r"(1024u), "r"(mbar) : "memory");
    }

    // ---- 3. B fragments (weights) for all 32 K-steps, loaded DURING flight.
    // b0: (k=tg, n=gid); b1: (k=tg+4, n=gid). All L1/L2 hits after warmup.
    const float* wb = Wh + (size_t)k * (D_DIM * V_DIM);
    uint32_t b0[32], b1[32];
    #pragma unroll
    for (int kk = 0; kk < 32; ++kk) {
        b0[kk] = f2tf32(wb[(kk * 8 + tg    ) * V_DIM + gid]);
        b1[kk] = f2tf32(wb[(kk * 8 + tg + 4) * V_DIM + gid]);
    }
    const float bv0 = bias[k * V_DIM + 2 * tg];
    const float bv1 = bias[k * V_DIM + 2 * tg + 1];

    // ---- 4. Wait for the 16 bulk copies (acquire -> generic LDS reads valid).
    {
        uint32_t done;
        asm volatile(
            "{\n\t.reg .pred p;\n\t"
            "mbarrier.try_wait.parity.acquire.cta.shared::cta.b64 p, [%1], 0;\n\t"
            "selp.b32 %0, 1, 0, p;\n\t}"
            : "=r"(done) : "r"(mbar) : "memory");
        if (!done) {
            asm volatile(
                "{\n\t.reg .pred P;\n\t"
                "W%=:\n\t"
                "mbarrier.try_wait.parity.acquire.cta.shared::cta.b64 P, [%0], 0, 0x989680;\n\t"
                "@P bra D%=;\n\tbra W%=;\n\tD%=:\n\t}"
                :: "r"(mbar) : "memory");
        }
    }

    // ---- 5. 32 x mma.sync m16n8k8 tf32, two alternating accumulators.
    // A-frag LDS at (row, col): stride-260 padding keeps the warp's 32
    // addresses on 32 distinct banks (conflict-free).
    const float* arow = wbase + gid * ROW_F + tg;
    float e0 = 0.f, e1 = 0.f, e2 = 0.f, e3 = 0.f;
    float q0 = 0.f, q1 = 0.f, q2 = 0.f, q3 = 0.f;
    #pragma unroll
    for (int kk = 0; kk < 32; ++kk) {
        const float* p = arow + kk * 8;
        uint32_t a0 = f2tf32(p[0]);
        uint32_t a2 = f2tf32(p[4]);
        uint32_t a1 = f2tf32(p[8 * ROW_F]);
        uint32_t a3 = f2tf32(p[8 * ROW_F + 4]);
        if (kk & 1) {
            asm("mma.sync.aligned.m16n8k8.row.col.f32.tf32.tf32.f32 "
                "{%0,%1,%2,%3}, {%4,%5,%6,%7}, {%8,%9}, {%0,%1,%2,%3};"
                : "+f"(q0), "+f"(q1), "+f"(q2), "+f"(q3)
                : "r"(a0), "r"(a1), "r"(a2), "r"(a3), "r"(b0[kk]), "r"(b1[kk]));
        } else {
            asm("mma.sync.aligned.m16n8k8.row.col.f32.tf32.tf32.f32 "
                "{%0,%1,%2,%3}, {%4,%5,%6,%7}, {%8,%9}, {%0,%1,%2,%3};"
                : "+f"(e0), "+f"(e1), "+f"(e2), "+f"(e3)
                : "r"(a0), "r"(a1), "r"(a2), "r"(a3), "r"(b0[kk]), "r"(b1[kk]));
        }
    }

    // ---- 6. Epilogue: combine accumulators + bias; float2 stores.
    // D layout: (row gid, cols 2tg,2tg+1) and (row gid+8, same cols).
    const float d0 = e0 + q0 + bv0;
    const float d1 = e1 + q1 + bv1;
    const float d2 = e2 + q2 + bv0;
    const float d3 = e3 + q3 + bv1;
    float2* o_lo = (float2*)(out + ((size_t)k * S_LEN + s0w + gid) * V_DIM + 2 * tg);
    float2* o_hi = (float2*)(out + ((size_t)k * S_LEN + s0w + gid + 8) * V_DIM + 2 * tg);
    *o_lo = make_float2(d0, d1);
    *o_hi = make_float2(d2, d3);
}

extern "C" void kernel_launch(void* const* d_in, const int* in_sizes, int n_in,
                              void* d_out, int out_size) {
    // metadata order: block_type_grid (unused), features, mask_idx, head_weights, head_bias
    const float* feats    = (const float*)d_in[1];
    const int*   mask_idx = (const int*)  d_in[2];
    const float* Wh       = (const float*)d_in[3];
    const float* bias     = (const float*)d_in[4];
    float*       out      = (float*)d_out;

    cudaFuncSetAttribute(attr_decoder_hmma,
                         cudaFuncAttributeMaxDynamicSharedMemorySize, SMEM_BYTES);
    dim3 grid(S_LEN / ROWS_CTA, K_HEADS);   // 256 x 24 CTAs, 64 rows each
    attr_decoder_hmma<<<grid, 128, SMEM_BYTES>>>(feats, mask_idx, Wh, bias, out);
}

// round 15
// speedup vs baseline: 2.5274x; 1.0464x over previous
#include <cuda_runtime.h>
#include <cstdint>

#define S_LEN 16384
#define D_DIM 256
#define V_DIM 8
#define K_HEADS 24
#define ROW_F 260                              // padded smem row stride (1040 B)
#define ROWS_TILE 16
#define T_ITER 8                               // tiles per warp
#define WARPS_CTA 2
#define ROWS_CTA (WARPS_CTA * ROWS_TILE * T_ITER)   // 256 rows per CTA
#define TILE_B (ROWS_TILE * ROW_F * 4)         // 16640 B
#define MBAR_PAD 128
#define SMEM_BYTES (MBAR_PAD + WARPS_CTA * 2 * TILE_B)   // 128 + 66560

__device__ __forceinline__ uint32_t f2tf32(float f) {
    uint32_t u;
    asm("cvt.rna.tf32.f32 %0, %1;" : "=r"(u) : "f"(f));
    return u;
}

__global__ __launch_bounds__(64, 3)
void attr_decoder_hmma(const float* __restrict__ feats,      // [N, 256]
                       const int*   __restrict__ mask_idx,   // [24, 16384]
                       const float* __restrict__ Wh,         // [24, 256, 8]
                       const float* __restrict__ bias,       // [24, 8]
                       float*       __restrict__ out)        // [24, 16384, 8]
{
    extern __shared__ __align__(16) char smem[];
    const int k    = blockIdx.y;
    const int lane = threadIdx.x & 31;
    const int warp = threadIdx.x >> 5;         // 0..1
    const int sct  = blockIdx.x * ROWS_CTA;    // CTA's first row (256-row span)

    const int tg  = lane & 3;                  // k-col / out-col pair
    const int gid = lane >> 2;                 // row in half-tile / v for B

    const uint32_t sbase = (uint32_t)__cvta_generic_to_shared(smem);
    const uint32_t mbar0 = sbase + warp * 32;  // warp's 2 mbars at +0, +16
    float* bufp[2] = {
        (float*)(smem + MBAR_PAD + (warp * 2 + 0) * TILE_B),
        (float*)(smem + MBAR_PAD + (warp * 2 + 1) * TILE_B)};
    const uint32_t bufs[2] = {
        (uint32_t)__cvta_generic_to_shared(bufp[0]),
        (uint32_t)__cvta_generic_to_shared(bufp[1])};

    // ---- 1. Warp-private mbarriers.
    if (lane == 0) {
        asm volatile("mbarrier.init.shared.b64 [%0], 1;" :: "r"(mbar0) : "memory");
        asm volatile("mbarrier.init.shared.b64 [%0], 1;" :: "r"(mbar0 + 16) : "memory");
    }
    __syncwarp();

    // ---- 2. Preload this warp's 128 gather indices (lane<16 holds iter r's row).
    int myidx[T_ITER];
    #pragma unroll
    for (int r = 0; r < T_ITER; ++r)
        myidx[r] = mask_idx[(size_t)k * S_LEN + sct + r * (WARPS_CTA * ROWS_TILE)
                            + warp * ROWS_TILE + (lane & 15)];

    // Bulk-gather one 16-row tile into buffer b.
    auto issue = [&](int r, int b) {
        if (lane == 0)
            asm volatile("mbarrier.arrive.expect_tx.shared.b64 _, [%0], %1;"
                         :: "r"(mbar0 + b * 16), "r"(ROWS_TILE * 1024u) : "memory");
        __syncwarp();
        if (lane < ROWS_TILE) {
            const float* src = feats + (size_t)myidx[r] * D_DIM;
            asm volatile(
                "cp.async.bulk.shared::cta.global.mbarrier::complete_tx::bytes "
                "[%0], [%1], %2, [%3];"
                :: "r"(bufs[b] + lane * (ROW_F * 4)), "l"(src), "r"(1024u),
                   "r"(mbar0 + b * 16) : "memory");
        }
    };

    // ---- 3. Prologue: tile 0 in flight, then load B fragments (amortized
    //      over all 8 tiles) while the first TMA flies.
    issue(0, 0);

    const float* wb = Wh + (size_t)k * (D_DIM * V_DIM);
    uint32_t b0[32], b1[32];
    #pragma unroll
    for (int kk = 0; kk < 32; ++kk) {
        b0[kk] = f2tf32(wb[(kk * 8 + tg    ) * V_DIM + gid]);
        b1[kk] = f2tf32(wb[(kk * 8 + tg + 4) * V_DIM + gid]);
    }
    const float bv0 = bias[k * V_DIM + 2 * tg];
    const float bv1 = bias[k * V_DIM + 2 * tg + 1];

    // ---- 4. Pipelined main loop: wait cur -> issue next -> MMA cur -> store.
    #pragma unroll
    for (int r = 0; r < T_ITER; ++r) {
        const int b = r & 1;
        const uint32_t mb = mbar0 + b * 16;
        const uint32_t ph = (r >> 1) & 1;
        {
            uint32_t done;
            asm volatile(
                "{\n\t.reg .pred p;\n\t"
                "mbarrier.try_wait.parity.acquire.cta.shared::cta.b64 p, [%1], %2;\n\t"
                "selp.b32 %0, 1, 0, p;\n\t}"
                : "=r"(done) : "r"(mb), "r"(ph) : "memory");
            if (!done) {
                asm volatile(
                    "{\n\t.reg .pred P;\n\t"
                    "W%=:\n\t"
                    "mbarrier.try_wait.parity.acquire.cta.shared::cta.b64 P, [%0], %1, 0x989680;\n\t"
                    "@P bra D%=;\n\tbra W%=;\n\tD%=:\n\t}"
                    :: "r"(mb), "r"(ph) : "memory");
            }
        }

        // Overlap: next tile's gather flies during this tile's MMAs.
        if (r + 1 < T_ITER) issue(r + 1, b ^ 1);

        // 32 x mma.sync m16n8k8 tf32; stride-260 padding -> conflict-free LDS.
        const float* arow = bufp[b] + gid * ROW_F + tg;
        float e0 = 0.f, e1 = 0.f, e2 = 0.f, e3 = 0.f;
        float q0 = 0.f, q1 = 0.f, q2 = 0.f, q3 = 0.f;
        #pragma unroll
        for (int kk = 0; kk < 32; ++kk) {
            const float* p = arow + kk * 8;
            uint32_t a0 = f2tf32(p[0]);
            uint32_t a2 = f2tf32(p[4]);
            uint32_t a1 = f2tf32(p[8 * ROW_F]);
            uint32_t a3 = f2tf32(p[8 * ROW_F + 4]);
            if (kk & 1) {
                asm("mma.sync.aligned.m16n8k8.row.col.f32.tf32.tf32.f32 "
                    "{%0,%1,%2,%3}, {%4,%5,%6,%7}, {%8,%9}, {%0,%1,%2,%3};"
                    : "+f"(q0), "+f"(q1), "+f"(q2), "+f"(q3)
                    : "r"(a0), "r"(a1), "r"(a2), "r"(a3), "r"(b0[kk]), "r"(b1[kk]));
            } else {
                asm("mma.sync.aligned.m16n8k8.row.col.f32.tf32.tf32.f32 "
                    "{%0,%1,%2,%3}, {%4,%5,%6,%7}, {%8,%9}, {%0,%1,%2,%3};"
                    : "+f"(e0), "+f"(e1), "+f"(e2), "+f"(e3)
                    : "r"(a0), "r"(a1), "r"(a2), "r"(a3), "r"(b0[kk]), "r"(b1[kk]));
            }
        }

        const int s0 = sct + r * (WARPS_CTA * ROWS_TILE) + warp * ROWS_TILE;
        const float d0 = e0 + q0 + bv0;
        const float d1 = e1 + q1 + bv1;
        const float d2 = e2 + q2 + bv0;
        const float d3 = e3 + q3 + bv1;
        float2* o_lo = (float2*)(out + ((size_t)k * S_LEN + s0 + gid) * V_DIM + 2 * tg);
        float2* o_hi = (float2*)(out + ((size_t)k * S_LEN + s0 + gid + 8) * V_DIM + 2 * tg);
        *o_lo = make_float2(d0, d1);
        *o_hi = make_float2(d2, d3);
    }
}

extern "C" void kernel_launch(void* const* d_in, const int* in_sizes, int n_in,
                              void* d_out, int out_size) {
    // metadata order: block_type_grid (unused), features, mask_idx, head_weights, head_bias
    const float* feats    = (const float*)d_in[1];
    const int*   mask_idx = (const int*)  d_in[2];
    const float* Wh       = (const float*)d_in[3];
    const float* bias     = (const float*)d_in[4];
    float*       out      = (float*)d_out;

    cudaFuncSetAttribute(attr_decoder_hmma,
                         cudaFuncAttributeMaxDynamicSharedMemorySize, SMEM_BYTES);
    dim3 grid(S_LEN / ROWS_CTA, K_HEADS);   // 64 x 24 CTAs, 256 rows each
    attr_decoder_hmma<<<grid, 64, SMEM_BYTES>>>(feats, mask_idx, Wh, bias, out);
}